// round 14
// baseline (speedup 1.0000x reference)
#include <cuda_runtime.h>
#include <cuda_fp16.h>
#include <math.h>
#include <stdint.h>

// MidGCN on GB300 (compute_103 PTX => mma.sync fp16 HMMA):
//   adj_f = 0.5*I - 0.5*P - P^2,  P = drow ∘ adj ∘ dcol
//   layer1: H = relu(0.5*X1 - 0.5*T1 - P@T1),  X1 = x@W1, T1 = P@X1
//   layer2: out = log_softmax(0.5*Z - 0.5*(P@Z) - P@(P@Z) + b2), Z = H@W2
// adj stored ONCE as unscaled fp16 (adj_h); drow/dcol folded into the skinny
// B operands and fp32 epilogues => single adj read for sums+conversion.
// Big GEMMs: single-product fp16 HMMA, BM=128 BN=128, K-SPLIT=2 (256 CTAs).

#define NROWS 8192
#define NHIDD 256
#define NFEATD 512

// ---------------- scratch (device globals) ----------------------------------
__device__ float g_rowpart[8 * NROWS];
__device__ float g_colpart[64 * NROWS];
__device__ float g_drow[NROWS];
__device__ float g_dcol[NROWS];
__device__ float g_X1[NROWS * NHIDD];
__device__ float g_T1[NROWS * NHIDD];
__device__ float g_Part[2 * NROWS * NHIDD];        // K-split partial outputs
__device__ __half g_adjh[(size_t)NROWS * NROWS];   // adj fp16 (unscaled)
__device__ __half g_xh[NROWS * NFEATD];            // x fp16
__device__ __half g_W1Thi[NHIDD * NFEATD];         // W1^T hi/lo
__device__ __half g_W1Tlo[NHIDD * NFEATD];
__device__ __half g_Bt1[NHIDD * NROWS];            // (dcol ∘ X1)^T fp16
__device__ __half g_Bt2[NHIDD * NROWS];            // (dcol ∘ T1)^T fp16
__device__ float2 g_Z  [NROWS];
__device__ float2 g_Zc [NROWS];
__device__ float2 g_U1 [NROWS];
__device__ float2 g_U1c[NROWS];

// ---------------- helpers ----------------------------------------------------
__device__ __forceinline__ uint32_t smem_u32(const void* p) {
    return (uint32_t)__cvta_generic_to_shared(p);
}
__device__ __forceinline__ void cp16(uint32_t s, const void* g) {
    asm volatile("cp.async.cg.shared.global [%0], [%1], 16;"
                 :: "r"(s), "l"(__cvta_generic_to_global(g)) : "memory");
}
#define CP_COMMIT() asm volatile("cp.async.commit_group;" ::: "memory")
#define CP_WAIT(n)  asm volatile("cp.async.wait_group %0;" :: "n"(n) : "memory")

__device__ __forceinline__ void ldmx4(uint32_t& r0, uint32_t& r1, uint32_t& r2, uint32_t& r3,
                                      uint32_t addr) {
    asm volatile("ldmatrix.sync.aligned.m8n8.x4.shared.b16 {%0,%1,%2,%3}, [%4];"
                 : "=r"(r0), "=r"(r1), "=r"(r2), "=r"(r3) : "r"(addr));
}
__device__ __forceinline__ void mma_f16(float* d, const uint32_t* a, const uint32_t* b) {
    asm volatile(
        "mma.sync.aligned.m16n8k16.row.col.f32.f16.f16.f32 "
        "{%0,%1,%2,%3}, {%4,%5,%6,%7}, {%8,%9}, {%0,%1,%2,%3};"
        : "+f"(d[0]), "+f"(d[1]), "+f"(d[2]), "+f"(d[3])
        : "r"(a[0]), "r"(a[1]), "r"(a[2]), "r"(a[3]), "r"(b[0]), "r"(b[1]));
}
__device__ __forceinline__ uint32_t sw128(uint32_t off) {
    return off ^ ((off >> 3) & 0x70);
}

// ---- fused: one adj pass -> adj_h (fp16) + row/col partial sums -------------
// Tile 128 rows x 1024 cols per CTA (grid 8 x 64). Phase 1: vectorized
// convert + column sums (float4 per thread). Phase 2: row sums from the
// L2-resident tile.
__global__ __launch_bounds__(256, 2)
void fused_sum_convert(const float* __restrict__ adj, __half* __restrict__ adjh,
                       float* __restrict__ rowpart, float* __restrict__ colpart) {
    int cb = blockIdx.x;          // 0..7   (1024-col stripe)
    int rb = blockIdx.y;          // 0..63  (128-row stripe)
    int r0 = rb * 128;
    int c4 = cb * 256 + threadIdx.x;         // float4 column-group index
    const float4* src = (const float4*)adj;
    uint2* dst = (uint2*)adjh;
    float4 cs = make_float4(0.f, 0.f, 0.f, 0.f);
    #pragma unroll 8
    for (int r = r0; r < r0 + 128; r++) {
        size_t i = (size_t)r * (NROWS / 4) + c4;
        float4 v = src[i];
        cs.x += v.x; cs.y += v.y; cs.z += v.z; cs.w += v.w;
        __half2 h0 = __floats2half2_rn(v.x, v.y);
        __half2 h1 = __floats2half2_rn(v.z, v.w);
        uint2 o;
        o.x = *(uint32_t*)&h0;
        o.y = *(uint32_t*)&h1;
        __stcs(&dst[i], o);
    }
    ((float4*)&colpart[(size_t)rb * NROWS])[c4] = cs;
    if (threadIdx.x < 128) {
        int r = r0 + threadIdx.x;
        const float4* rp = (const float4*)(adj + (size_t)r * NROWS + cb * 1024);
        float t = 0.f;
        #pragma unroll 8
        for (int i = 0; i < 256; i++) {
            float4 v = rp[i];
            t += (v.x + v.y) + (v.z + v.w);
        }
        rowpart[(size_t)cb * NROWS + r] = t;
    }
}

// drow/dcol = sum^-0.5 (inf -> 0)
__global__ void dscale_kernel(const float* __restrict__ rowpart, const float* __restrict__ colpart,
                              float* __restrict__ drow, float* __restrict__ dcol) {
    int i = blockIdx.x * 256 + threadIdx.x;
    float rs = 0.f;
    #pragma unroll
    for (int p = 0; p < 8; p++) rs += rowpart[(size_t)p * NROWS + i];
    drow[i] = rs > 0.f ? rsqrtf(rs) : 0.f;
    float cs = 0.f;
    #pragma unroll
    for (int p = 0; p < 64; p++) cs += colpart[(size_t)p * NROWS + i];
    dcol[i] = cs > 0.f ? rsqrtf(cs) : 0.f;
}

// ---------------- x -> fp16 --------------------------------------------------
__global__ void convert_x(const float* __restrict__ x, __half* __restrict__ xh) {
    size_t i4 = (size_t)blockIdx.x * 256 + threadIdx.x;
    float4 v = ((const float4*)x)[i4];
    __half2 h0 = __floats2half2_rn(v.x, v.y);
    __half2 h1 = __floats2half2_rn(v.z, v.w);
    uint2 o;
    o.x = *(uint32_t*)&h0;
    o.y = *(uint32_t*)&h1;
    ((uint2*)xh)[i4] = o;
}

// ---- transpose + fp16 split; optional per-source-row scale (rowScale) -------
template<bool WRITE_LO>
__global__ void trans_split(const float* __restrict__ src,
                            __half* __restrict__ hi, __half* __restrict__ lo,
                            const float* __restrict__ rowScale, int srcN) {
    __shared__ float tile[32][33];
    int m0 = blockIdx.x * 32, n0 = blockIdx.y * 32;
    int dstStride = gridDim.x * 32;
    int tx = threadIdx.x, ty = threadIdx.y;   // 32 x 8
    #pragma unroll
    for (int j = 0; j < 4; j++)
        tile[ty + j * 8][tx] = src[(size_t)(m0 + ty + j * 8) * srcN + n0 + tx];
    __syncthreads();
    float rs = rowScale ? rowScale[m0 + tx] : 1.0f;
    #pragma unroll
    for (int j = 0; j < 4; j++) {
        int n = n0 + ty + j * 8;
        float v = tile[tx][ty + j * 8] * rs;
        __half h = __float2half_rn(v);
        size_t o = (size_t)n * dstStride + m0 + tx;
        hi[o] = h;
        if (WRITE_LO) lo[o] = __float2half_rn(v - __half2float(h));
    }
}

// ---- fused: T1 = drow∘(Part0+Part1); Bt2 = (dcol ∘ T1)^T fp16 ---------------
__global__ void trans_combine(const float* __restrict__ p0, const float* __restrict__ p1,
                              const float* __restrict__ drow, const float* __restrict__ dcol,
                              float* __restrict__ T1, __half* __restrict__ Bt) {
    __shared__ float tile[32][33];
    int m0 = blockIdx.x * 32, n0 = blockIdx.y * 32;
    int tx = threadIdx.x, ty = threadIdx.y;   // 32 x 8
    #pragma unroll
    for (int j = 0; j < 4; j++) {
        int m = m0 + ty + j * 8;
        size_t idx = (size_t)m * NHIDD + n0 + tx;
        float v = drow[m] * (p0[idx] + p1[idx]);
        tile[ty + j * 8][tx] = v;
        T1[idx] = v;
    }
    __syncthreads();
    float dc = dcol[m0 + tx];
    #pragma unroll
    for (int j = 0; j < 4; j++) {
        int n = n0 + ty + j * 8;
        float v = tile[tx][ty + j * 8] * dc;
        Bt[(size_t)n * NROWS + m0 + tx] = __float2half_rn(v);
    }
}

// ---------------- HMMA GEMM: C[128x128/CTA] = A_f16 @ (Bhi [+ Blo])^T -------
// BM=128, BN=128, BK=64, SW128 smem, 8 warps (4M x 2N), warp tile 32x64.
// NPROD=1: 3-stage pipeline; NPROD=2: 2-stage.
// blockIdx.z = K-split index (Ksub = K / gridDim.z), output slab per z.
#define GK 64
#define TILE_BYTES 16384                 // 128 rows * 128B

template<int NPROD>
__global__ __launch_bounds__(256, 2)
void gemmNP(const __half* __restrict__ A_g,
            const __half* __restrict__ Bhi_g, const __half* __restrict__ Blo_g,
            float* __restrict__ C_g, int K) {
    const int STAGE = TILE_BYTES * (1 + NPROD);
    const int NSTAGE = (NPROD == 1) ? 3 : 2;
    extern __shared__ __align__(1024) char smem[];
    const int tid = threadIdx.x, lane = tid & 31, wid = tid >> 5;
    const int wm = wid >> 1;          // 0..3
    const int wn = wid & 1;           // 0..1
    const int blockM = blockIdx.x * 128;
    const int blockN = blockIdx.y * 128;
    const int Ksub = K / gridDim.z;
    const int kBase = blockIdx.z * Ksub;
    float* C = C_g + (size_t)blockIdx.z * NROWS * NHIDD;
    const uint32_t sbase = smem_u32(smem);

    const __half* A   = A_g   + (size_t)blockM * K;
    const __half* Bhi = Bhi_g + (size_t)blockN * K;
    const __half* Blo = (NPROD == 2) ? Blo_g + (size_t)blockN * K : nullptr;

    float d[2][8][4];
    #pragma unroll
    for (int mt = 0; mt < 2; mt++)
        #pragma unroll
        for (int nt = 0; nt < 8; nt++)
            #pragma unroll
            for (int e = 0; e < 4; e++) d[mt][nt][e] = 0.f;

    auto load_stage = [&](int it, int buf) {
        uint32_t stg = sbase + (uint32_t)buf * STAGE;
        int k0 = kBase + it * GK;
        #pragma unroll
        for (int idx = tid; idx < 1024; idx += 256) {
            int row = idx >> 3, g = idx & 7;
            cp16(stg + sw128((uint32_t)(row * 128 + g * 16)),
                 A + (size_t)row * K + k0 + g * 8);
        }
        #pragma unroll
        for (int idx = tid; idx < 1024; idx += 256) {
            int row = idx >> 3, g = idx & 7;
            cp16(stg + TILE_BYTES + sw128((uint32_t)(row * 128 + g * 16)),
                 Bhi + (size_t)row * K + k0 + g * 8);
        }
        if (NPROD == 2) {
            #pragma unroll
            for (int idx = tid; idx < 1024; idx += 256) {
                int row = idx >> 3, g = idx & 7;
                cp16(stg + 2 * TILE_BYTES + sw128((uint32_t)(row * 128 + g * 16)),
                     Blo + (size_t)row * K + k0 + g * 8);
            }
        }
        CP_COMMIT();
    };

    const int rowA = wm * 32 + (lane & 15);
    const int kbA  = (lane >> 4) * 16;
    const int rowB = wn * 64 + (lane & 7) + ((lane >> 4) & 1) * 8;
    const int kbB  = ((lane >> 3) & 1) * 16;

    const int NIT = Ksub / GK;
    load_stage(0, 0);
    if (NSTAGE == 3) load_stage(1, 1);

    for (int it = 0; it < NIT; ++it) {
        if (NSTAGE == 3) {
            if (it + 2 < NIT) { load_stage(it + 2, (it + 2) % 3); CP_WAIT(2); }
            else if (it + 1 < NIT) { CP_WAIT(1); }
            else { CP_WAIT(0); }
        } else {
            if (it + 1 < NIT) { load_stage(it + 1, (it + 1) & 1); CP_WAIT(1); }
            else { CP_WAIT(0); }
        }
        __syncthreads();

        uint32_t stg = sbase + (uint32_t)(it % NSTAGE) * STAGE;
        const uint32_t sA = stg;
        const uint32_t sBhi = stg + TILE_BYTES;
        const uint32_t sBlo = stg + 2 * TILE_BYTES;

        #pragma unroll
        for (int ks = 0; ks < 4; ks++) {
            uint32_t a[2][4];
            #pragma unroll
            for (int mt = 0; mt < 2; mt++) {
                uint32_t off = sw128((uint32_t)((rowA + mt * 16) * 128 + ks * 32 + kbA));
                ldmx4(a[mt][0], a[mt][1], a[mt][2], a[mt][3], sA + off);
            }
            uint32_t bh[8][2];
            #pragma unroll
            for (int p = 0; p < 4; p++) {
                uint32_t off = sw128((uint32_t)((rowB + p * 16) * 128 + ks * 32 + kbB));
                ldmx4(bh[2*p][0], bh[2*p][1], bh[2*p+1][0], bh[2*p+1][1], sBhi + off);
            }
            #pragma unroll
            for (int mt = 0; mt < 2; mt++)
                #pragma unroll
                for (int nt = 0; nt < 8; nt++)
                    mma_f16(d[mt][nt], a[mt], bh[nt]);
            if (NPROD == 2) {
                uint32_t bl[8][2];
                #pragma unroll
                for (int p = 0; p < 4; p++) {
                    uint32_t off = sw128((uint32_t)((rowB + p * 16) * 128 + ks * 32 + kbB));
                    ldmx4(bl[2*p][0], bl[2*p][1], bl[2*p+1][0], bl[2*p+1][1], sBlo + off);
                }
                #pragma unroll
                for (int mt = 0; mt < 2; mt++)
                    #pragma unroll
                    for (int nt = 0; nt < 8; nt++)
                        mma_f16(d[mt][nt], a[mt], bl[nt]);
            }
        }
        __syncthreads();
    }

    const int q = lane >> 2, c2 = (lane & 3) * 2;
    #pragma unroll
    for (int mt = 0; mt < 2; mt++) {
        int m0 = blockM + wm * 32 + mt * 16 + q;
        #pragma unroll
        for (int nt = 0; nt < 8; nt++) {
            int col = blockN + wn * 64 + nt * 8 + c2;
            *(float2*)&C[(size_t)m0 * NHIDD + col] = make_float2(d[mt][nt][0], d[mt][nt][1]);
            *(float2*)&C[(size_t)(m0 + 8) * NHIDD + col] = make_float2(d[mt][nt][2], d[mt][nt][3]);
        }
    }
}

// ---- layer-1 epilogue + Z = H@W2 fused (sums raw ACC partials, applies drow)
__global__ void epi2_kernel(const float* __restrict__ ACC0, const float* __restrict__ ACC1,
                            const float* __restrict__ X1,
                            const float* __restrict__ T1, const float* __restrict__ W2,
                            const float* __restrict__ drow, const float* __restrict__ dcol,
                            float2* __restrict__ Z, float2* __restrict__ Zc) {
    int warp = threadIdx.x >> 5, lane = threadIdx.x & 31;
    int row = blockIdx.x * 8 + warp;
    size_t base = (size_t)row * NHIDD;
    float dr = drow[row];
    float z0 = 0.f, z1 = 0.f;
    #pragma unroll
    for (int b = 0; b < 2; b++) {
        int n0 = lane * 8 + b * 4;
        float4 a0 = *(const float4*)&ACC0[base + n0];
        float4 a1 = *(const float4*)&ACC1[base + n0];
        float4 xv = *(const float4*)&X1[base + n0];
        float4 tv = *(const float4*)&T1[base + n0];
        float as[4] = {dr * (a0.x + a1.x), dr * (a0.y + a1.y),
                       dr * (a0.z + a1.z), dr * (a0.w + a1.w)};
        float xs[4] = {xv.x, xv.y, xv.z, xv.w};
        float ts[4] = {tv.x, tv.y, tv.z, tv.w};
        #pragma unroll
        for (int e = 0; e < 4; e++) {
            float h = 0.5f * xs[e] - 0.5f * ts[e] - as[e];
            h = h > 0.f ? h : 0.f;
            int n = n0 + e;
            z0 = fmaf(h, W2[2 * n], z0);
            z1 = fmaf(h, W2[2 * n + 1], z1);
        }
    }
    #pragma unroll
    for (int o = 16; o > 0; o >>= 1) {
        z0 += __shfl_xor_sync(0xffffffffu, z0, o);
        z1 += __shfl_xor_sync(0xffffffffu, z1, o);
    }
    if (lane == 0) {
        Z[row] = make_float2(z0, z1);
        float dc = dcol[row];
        Zc[row] = make_float2(dc * z0, dc * z1);
    }
}

// ---- U = drow ∘ (adj_h @ V), V [8192,2] already dcol-scaled -----------------
template<int FINAL>
__global__ void pv16(const __half* __restrict__ adjh, const float2* __restrict__ V,
                     const float2* __restrict__ Z, const float2* __restrict__ U1,
                     const float* __restrict__ b2,
                     const float* __restrict__ drow, const float* __restrict__ dcol,
                     float2* __restrict__ outU, float2* __restrict__ outUc,
                     float* __restrict__ out) {
    int warp = threadIdx.x >> 5, lane = threadIdx.x & 31;
    int row = blockIdx.x * 8 + warp;
    const uint4* ap = (const uint4*)(adjh + (size_t)row * NROWS);
    float ax = 0.f, ay = 0.f;
    #pragma unroll 1
    for (int ii = 0; ii < NROWS / 8; ii += 128) {
        uint4 q[4];
        #pragma unroll
        for (int j = 0; j < 4; j++)
            q[j] = __ldcs(&ap[ii + j * 32 + lane]);
        #pragma unroll
        for (int j = 0; j < 4; j++) {
            int k = (ii + j * 32 + lane) * 8;
            float2 f0 = __half22float2(*(__half2*)&q[j].x);
            float2 f1 = __half22float2(*(__half2*)&q[j].y);
            float2 f2 = __half22float2(*(__half2*)&q[j].z);
            float2 f3 = __half22float2(*(__half2*)&q[j].w);
            float2 v0 = V[k],     v1 = V[k + 1], v2 = V[k + 2], v3 = V[k + 3];
            float2 v4 = V[k + 4], v5 = V[k + 5], v6 = V[k + 6], v7 = V[k + 7];
            ax += f0.x * v0.x + f0.y * v1.x + f1.x * v2.x + f1.y * v3.x
                + f2.x * v4.x + f2.y * v5.x + f3.x * v6.x + f3.y * v7.x;
            ay += f0.x * v0.y + f0.y * v1.y + f1.x * v2.y + f1.y * v3.y
                + f2.x * v4.y + f2.y * v5.y + f3.x * v6.y + f3.y * v7.y;
        }
    }
    #pragma unroll
    for (int o = 16; o > 0; o >>= 1) {
        ax += __shfl_xor_sync(0xffffffffu, ax, o);
        ay += __shfl_xor_sync(0xffffffffu, ay, o);
    }
    if (lane == 0) {
        float dr = drow[row];
        float ux = dr * ax, uy = dr * ay;
        if (FINAL == 0) {
            outU[row] = make_float2(ux, uy);
            float dc = dcol[row];
            outUc[row] = make_float2(dc * ux, dc * uy);
        } else {
            float2 z = Z[row];
            float2 u1 = U1[row];
            float l0 = 0.5f * z.x - 0.5f * u1.x - ux + b2[0];
            float l1 = 0.5f * z.y - 0.5f * u1.y - uy + b2[1];
            float mx = fmaxf(l0, l1);
            float lse = mx + logf(expf(l0 - mx) + expf(l1 - mx));
            out[2 * row + 0] = l0 - lse;
            out[2 * row + 1] = l1 - lse;
        }
    }
}

// ---------------- launcher --------------------------------------------------
extern "C" void kernel_launch(void* const* d_in, const int* in_sizes, int n_in,
                              void* d_out, int out_size) {
    const float* x   = (const float*)d_in[0];
    const float* adj = (const float*)d_in[1];
    const float* W1  = (const float*)d_in[2];
    const float* W2  = (const float*)d_in[3];
    const float* b2  = (const float*)d_in[4];
    float* out = (float*)d_out;

    float *rowpart, *colpart, *drow, *dcol, *X1, *T1, *Part;
    __half *adjh, *xh, *W1Thi, *W1Tlo, *Bt1, *Bt2;
    float2 *Z, *Zc, *U1, *U1c;
    cudaGetSymbolAddress((void**)&rowpart, g_rowpart);
    cudaGetSymbolAddress((void**)&colpart, g_colpart);
    cudaGetSymbolAddress((void**)&drow,    g_drow);
    cudaGetSymbolAddress((void**)&dcol,    g_dcol);
    cudaGetSymbolAddress((void**)&X1,      g_X1);
    cudaGetSymbolAddress((void**)&T1,      g_T1);
    cudaGetSymbolAddress((void**)&Part,    g_Part);
    cudaGetSymbolAddress((void**)&adjh,    g_adjh);
    cudaGetSymbolAddress((void**)&xh,      g_xh);
    cudaGetSymbolAddress((void**)&W1Thi,   g_W1Thi);
    cudaGetSymbolAddress((void**)&W1Tlo,   g_W1Tlo);
    cudaGetSymbolAddress((void**)&Bt1,     g_Bt1);
    cudaGetSymbolAddress((void**)&Bt2,     g_Bt2);
    cudaGetSymbolAddress((void**)&Z,       g_Z);
    cudaGetSymbolAddress((void**)&Zc,      g_Zc);
    cudaGetSymbolAddress((void**)&U1,      g_U1);
    cudaGetSymbolAddress((void**)&U1c,     g_U1c);

    float* Part0 = Part;
    float* Part1 = Part + (size_t)NROWS * NHIDD;

    const int SM1 = 3 * TILE_BYTES * 2;   // gemmNP<1>: 98304
    const int SM2 = 2 * TILE_BYTES * 3;   // gemmNP<2>: 98304
    cudaFuncSetAttribute(gemmNP<1>, cudaFuncAttributeMaxDynamicSharedMemorySize, SM1);
    cudaFuncSetAttribute(gemmNP<2>, cudaFuncAttributeMaxDynamicSharedMemorySize, SM2);

    // Side stream + events for fork/join (host resources, created once).
    static cudaStream_t sB = nullptr;
    static cudaEvent_t eFork = nullptr, eX1 = nullptr;
    if (sB == nullptr) {
        cudaStreamCreateWithFlags(&sB, cudaStreamNonBlocking);
        cudaEventCreateWithFlags(&eFork, cudaEventDisableTiming);
        cudaEventCreateWithFlags(&eX1, cudaEventDisableTiming);
    }

    // ---- fork: x-chain on side stream (independent of adj) ----
    cudaEventRecord(eFork, 0);
    cudaStreamWaitEvent(sB, eFork, 0);
    convert_x<<<(NROWS * (NFEATD / 4)) / 256, 256, 0, sB>>>(x, xh);
    trans_split<true><<<dim3(NFEATD / 32, NHIDD / 32), dim3(32, 8), 0, sB>>>(
        W1, W1Thi, W1Tlo, nullptr, NHIDD);
    // X1 = x @ W1 (2-product, K=512)
    gemmNP<2><<<dim3(NROWS / 128, NHIDD / 128, 1), 256, SM2, sB>>>(
        xh, W1Thi, W1Tlo, X1, NFEATD);
    cudaEventRecord(eX1, sB);

    // ---- main stream: one adj pass => adj_h + sums; then dcol/drow ----
    fused_sum_convert<<<dim3(8, 64), 256>>>(adj, adjh, rowpart, colpart);
    dscale_kernel<<<NROWS / 256, 256>>>(rowpart, colpart, drow, dcol);

    // Bt1 = (dcol ∘ X1)^T fp16  (needs X1 + dcol)
    cudaStreamWaitEvent(0, eX1, 0);
    trans_split<false><<<dim3(NROWS / 32, NHIDD / 32), dim3(32, 8)>>>(
        X1, Bt1, nullptr, dcol, NHIDD);

    // raw T1 partials = adj_h @ Bt1^T (K-split=2)
    gemmNP<1><<<dim3(NROWS / 128, NHIDD / 128, 2), 256, SM1>>>(adjh, Bt1, nullptr, Part, NROWS);

    // T1 = drow∘(Part0+Part1); Bt2 = (dcol ∘ T1)^T fp16
    trans_combine<<<dim3(NROWS / 32, NHIDD / 32), dim3(32, 8)>>>(
        Part0, Part1, drow, dcol, T1, Bt2);

    // raw ACC partials = adj_h @ Bt2^T (K-split=2; consumed by epi2)
    gemmNP<1><<<dim3(NROWS / 128, NHIDD / 128, 2), 256, SM1>>>(adjh, Bt2, nullptr, Part, NROWS);

    // H = relu(0.5*X1 - 0.5*T1 - drow∘(ACC0+ACC1)); Z = H@W2; Zc = dcol∘Z
    epi2_kernel<<<NROWS / 8, 256>>>(Part0, Part1, X1, T1, W2, drow, dcol, Z, Zc);

    // U1 = drow ∘ (adj_h @ Zc); U1c = dcol∘U1
    pv16<0><<<NROWS / 8, 256>>>(adjh, Zc, nullptr, nullptr, nullptr, drow, dcol,
                                U1, U1c, nullptr);

    // out = log_softmax(0.5*Z - 0.5*U1 - drow∘(adj_h @ U1c) + b2)
    pv16<1><<<NROWS / 8, 256>>>(adjh, U1c, Z, U1, b2, drow, dcol,
                                nullptr, nullptr, out);
}

// round 15
// speedup vs baseline: 1.0484x; 1.0484x over previous
#include <cuda_runtime.h>
#include <cuda_fp16.h>
#include <math.h>
#include <stdint.h>

// MidGCN on GB300 (compute_103 PTX => mma.sync fp16 HMMA):
//   adj_f = 0.5*I - 0.5*P - P^2,  P = drow ∘ adj ∘ dcol
//   layer1: H = relu(0.5*X1 - 0.5*T1 - P@T1),  X1 = x@W1, T1 = P@X1
//   layer2: out = log_softmax(0.5*Z - 0.5*(P@Z) - P@(P@Z) + b2), Z = H@W2
// adj stored ONCE as unscaled fp16 (adj_h); drow/dcol folded into the skinny
// B operands and fp32 epilogues => single adj read for sums+conversion.
// fused_sum_convert: 128x256 tile (L2-resident for phase-2 row sums),
// phase-1 vectorized (float4 loads, 4 row-subgroups x 64 col-groups).
// Big GEMMs: single-product fp16 HMMA, BM=128 BN=128, K-SPLIT=2 (256 CTAs).

#define NROWS 8192
#define NHIDD 256
#define NFEATD 512

// ---------------- scratch (device globals) ----------------------------------
__device__ float g_rowpart[32 * NROWS];
__device__ float g_colpart[256 * NROWS];
__device__ float g_drow[NROWS];
__device__ float g_dcol[NROWS];
__device__ float g_X1[NROWS * NHIDD];
__device__ float g_T1[NROWS * NHIDD];
__device__ float g_Part[2 * NROWS * NHIDD];        // K-split partial outputs
__device__ __half g_adjh[(size_t)NROWS * NROWS];   // adj fp16 (unscaled)
__device__ __half g_xh[NROWS * NFEATD];            // x fp16
__device__ __half g_W1Thi[NHIDD * NFEATD];         // W1^T hi/lo
__device__ __half g_W1Tlo[NHIDD * NFEATD];
__device__ __half g_Bt1[NHIDD * NROWS];            // (dcol ∘ X1)^T fp16
__device__ __half g_Bt2[NHIDD * NROWS];            // (dcol ∘ T1)^T fp16
__device__ float2 g_Z  [NROWS];
__device__ float2 g_Zc [NROWS];
__device__ float2 g_U1 [NROWS];
__device__ float2 g_U1c[NROWS];

// ---------------- helpers ----------------------------------------------------
__device__ __forceinline__ uint32_t smem_u32(const void* p) {
    return (uint32_t)__cvta_generic_to_shared(p);
}
__device__ __forceinline__ void cp16(uint32_t s, const void* g) {
    asm volatile("cp.async.cg.shared.global [%0], [%1], 16;"
                 :: "r"(s), "l"(__cvta_generic_to_global(g)) : "memory");
}
#define CP_COMMIT() asm volatile("cp.async.commit_group;" ::: "memory")
#define CP_WAIT(n)  asm volatile("cp.async.wait_group %0;" :: "n"(n) : "memory")

__device__ __forceinline__ void ldmx4(uint32_t& r0, uint32_t& r1, uint32_t& r2, uint32_t& r3,
                                      uint32_t addr) {
    asm volatile("ldmatrix.sync.aligned.m8n8.x4.shared.b16 {%0,%1,%2,%3}, [%4];"
                 : "=r"(r0), "=r"(r1), "=r"(r2), "=r"(r3) : "r"(addr));
}
__device__ __forceinline__ void mma_f16(float* d, const uint32_t* a, const uint32_t* b) {
    asm volatile(
        "mma.sync.aligned.m16n8k16.row.col.f32.f16.f16.f32 "
        "{%0,%1,%2,%3}, {%4,%5,%6,%7}, {%8,%9}, {%0,%1,%2,%3};"
        : "+f"(d[0]), "+f"(d[1]), "+f"(d[2]), "+f"(d[3])
        : "r"(a[0]), "r"(a[1]), "r"(a[2]), "r"(a[3]), "r"(b[0]), "r"(b[1]));
}
__device__ __forceinline__ uint32_t sw128(uint32_t off) {
    return off ^ ((off >> 3) & 0x70);
}

// ---- fused: one adj pass -> adj_h (fp16) + row/col partial sums -------------
// Tile 128 rows x 256 cols per CTA (grid 32 x 64; 128 KB => L2-resident).
// Phase 1: 4 row-subgroups x 64 float4 col-groups, 32 rows each, vectorized.
// Phase 2: row sums re-read the tile from L1/L2.
__global__ __launch_bounds__(256, 2)
void fused_sum_convert(const float* __restrict__ adj, __half* __restrict__ adjh,
                       float* __restrict__ rowpart, float* __restrict__ colpart) {
    int cb = blockIdx.x;          // 0..31 (256-col stripe)
    int rb = blockIdx.y;          // 0..63 (128-row stripe)
    int sub = threadIdx.x >> 6;   // 0..3  (row subgroup)
    int cg  = threadIdx.x & 63;   // 0..63 (float4 col-group in stripe)
    int c4 = cb * 64 + cg;
    int r0 = rb * 128 + sub * 32;
    const float4* src = (const float4*)adj;
    uint2* dst = (uint2*)adjh;
    float4 cs = make_float4(0.f, 0.f, 0.f, 0.f);
    #pragma unroll 8
    for (int r = r0; r < r0 + 32; r++) {
        size_t i = (size_t)r * (NROWS / 4) + c4;
        float4 v = src[i];
        cs.x += v.x; cs.y += v.y; cs.z += v.z; cs.w += v.w;
        __half2 h0 = __floats2half2_rn(v.x, v.y);
        __half2 h1 = __floats2half2_rn(v.z, v.w);
        uint2 o;
        o.x = *(uint32_t*)&h0;
        o.y = *(uint32_t*)&h1;
        __stcs(&dst[i], o);
    }
    ((float4*)&colpart[(size_t)(rb * 4 + sub) * NROWS])[c4] = cs;
    if (threadIdx.x < 128) {
        int r = rb * 128 + threadIdx.x;
        const float4* rp = (const float4*)(adj + (size_t)r * NROWS + cb * 256);
        float t = 0.f;
        #pragma unroll 8
        for (int i = 0; i < 64; i++) {
            float4 v = rp[i];
            t += (v.x + v.y) + (v.z + v.w);
        }
        rowpart[(size_t)cb * NROWS + r] = t;
    }
}

// drow/dcol = sum^-0.5 (inf -> 0)
__global__ void dscale_kernel(const float* __restrict__ rowpart, const float* __restrict__ colpart,
                              float* __restrict__ drow, float* __restrict__ dcol) {
    int i = blockIdx.x * 256 + threadIdx.x;
    float rs = 0.f;
    #pragma unroll
    for (int p = 0; p < 32; p++) rs += rowpart[(size_t)p * NROWS + i];
    drow[i] = rs > 0.f ? rsqrtf(rs) : 0.f;
    float cs = 0.f;
    #pragma unroll 16
    for (int p = 0; p < 256; p++) cs += colpart[(size_t)p * NROWS + i];
    dcol[i] = cs > 0.f ? rsqrtf(cs) : 0.f;
}

// ---------------- x -> fp16 --------------------------------------------------
__global__ void convert_x(const float* __restrict__ x, __half* __restrict__ xh) {
    size_t i4 = (size_t)blockIdx.x * 256 + threadIdx.x;
    float4 v = ((const float4*)x)[i4];
    __half2 h0 = __floats2half2_rn(v.x, v.y);
    __half2 h1 = __floats2half2_rn(v.z, v.w);
    uint2 o;
    o.x = *(uint32_t*)&h0;
    o.y = *(uint32_t*)&h1;
    ((uint2*)xh)[i4] = o;
}

// ---- transpose + fp16 split; optional per-source-row scale (rowScale) -------
template<bool WRITE_LO>
__global__ void trans_split(const float* __restrict__ src,
                            __half* __restrict__ hi, __half* __restrict__ lo,
                            const float* __restrict__ rowScale, int srcN) {
    __shared__ float tile[32][33];
    int m0 = blockIdx.x * 32, n0 = blockIdx.y * 32;
    int dstStride = gridDim.x * 32;
    int tx = threadIdx.x, ty = threadIdx.y;   // 32 x 8
    #pragma unroll
    for (int j = 0; j < 4; j++)
        tile[ty + j * 8][tx] = src[(size_t)(m0 + ty + j * 8) * srcN + n0 + tx];
    __syncthreads();
    float rs = rowScale ? rowScale[m0 + tx] : 1.0f;
    #pragma unroll
    for (int j = 0; j < 4; j++) {
        int n = n0 + ty + j * 8;
        float v = tile[tx][ty + j * 8] * rs;
        __half h = __float2half_rn(v);
        size_t o = (size_t)n * dstStride + m0 + tx;
        hi[o] = h;
        if (WRITE_LO) lo[o] = __float2half_rn(v - __half2float(h));
    }
}

// ---- fused: T1 = drow∘(Part0+Part1); Bt2 = (dcol ∘ T1)^T fp16 ---------------
__global__ void trans_combine(const float* __restrict__ p0, const float* __restrict__ p1,
                              const float* __restrict__ drow, const float* __restrict__ dcol,
                              float* __restrict__ T1, __half* __restrict__ Bt) {
    __shared__ float tile[32][33];
    int m0 = blockIdx.x * 32, n0 = blockIdx.y * 32;
    int tx = threadIdx.x, ty = threadIdx.y;   // 32 x 8
    #pragma unroll
    for (int j = 0; j < 4; j++) {
        int m = m0 + ty + j * 8;
        size_t idx = (size_t)m * NHIDD + n0 + tx;
        float v = drow[m] * (p0[idx] + p1[idx]);
        tile[ty + j * 8][tx] = v;
        T1[idx] = v;
    }
    __syncthreads();
    float dc = dcol[m0 + tx];
    #pragma unroll
    for (int j = 0; j < 4; j++) {
        int n = n0 + ty + j * 8;
        float v = tile[tx][ty + j * 8] * dc;
        Bt[(size_t)n * NROWS + m0 + tx] = __float2half_rn(v);
    }
}

// ---------------- HMMA GEMM: C[128x128/CTA] = A_f16 @ (Bhi [+ Blo])^T -------
// BM=128, BN=128, BK=64, SW128 smem, 8 warps (4M x 2N), warp tile 32x64.
// NPROD=1: 3-stage pipeline; NPROD=2: 2-stage.
// blockIdx.z = K-split index (Ksub = K / gridDim.z), output slab per z.
#define GK 64
#define TILE_BYTES 16384                 // 128 rows * 128B

template<int NPROD>
__global__ __launch_bounds__(256, 2)
void gemmNP(const __half* __restrict__ A_g,
            const __half* __restrict__ Bhi_g, const __half* __restrict__ Blo_g,
            float* __restrict__ C_g, int K) {
    const int STAGE = TILE_BYTES * (1 + NPROD);
    const int NSTAGE = (NPROD == 1) ? 3 : 2;
    extern __shared__ __align__(1024) char smem[];
    const int tid = threadIdx.x, lane = tid & 31, wid = tid >> 5;
    const int wm = wid >> 1;          // 0..3
    const int wn = wid & 1;           // 0..1
    const int blockM = blockIdx.x * 128;
    const int blockN = blockIdx.y * 128;
    const int Ksub = K / gridDim.z;
    const int kBase = blockIdx.z * Ksub;
    float* C = C_g + (size_t)blockIdx.z * NROWS * NHIDD;
    const uint32_t sbase = smem_u32(smem);

    const __half* A   = A_g   + (size_t)blockM * K;
    const __half* Bhi = Bhi_g + (size_t)blockN * K;
    const __half* Blo = (NPROD == 2) ? Blo_g + (size_t)blockN * K : nullptr;

    float d[2][8][4];
    #pragma unroll
    for (int mt = 0; mt < 2; mt++)
        #pragma unroll
        for (int nt = 0; nt < 8; nt++)
            #pragma unroll
            for (int e = 0; e < 4; e++) d[mt][nt][e] = 0.f;

    auto load_stage = [&](int it, int buf) {
        uint32_t stg = sbase + (uint32_t)buf * STAGE;
        int k0 = kBase + it * GK;
        #pragma unroll
        for (int idx = tid; idx < 1024; idx += 256) {
            int row = idx >> 3, g = idx & 7;
            cp16(stg + sw128((uint32_t)(row * 128 + g * 16)),
                 A + (size_t)row * K + k0 + g * 8);
        }
        #pragma unroll
        for (int idx = tid; idx < 1024; idx += 256) {
            int row = idx >> 3, g = idx & 7;
            cp16(stg + TILE_BYTES + sw128((uint32_t)(row * 128 + g * 16)),
                 Bhi + (size_t)row * K + k0 + g * 8);
        }
        if (NPROD == 2) {
            #pragma unroll
            for (int idx = tid; idx < 1024; idx += 256) {
                int row = idx >> 3, g = idx & 7;
                cp16(stg + 2 * TILE_BYTES + sw128((uint32_t)(row * 128 + g * 16)),
                     Blo + (size_t)row * K + k0 + g * 8);
            }
        }
        CP_COMMIT();
    };

    const int rowA = wm * 32 + (lane & 15);
    const int kbA  = (lane >> 4) * 16;
    const int rowB = wn * 64 + (lane & 7) + ((lane >> 4) & 1) * 8;
    const int kbB  = ((lane >> 3) & 1) * 16;

    const int NIT = Ksub / GK;
    load_stage(0, 0);
    if (NSTAGE == 3) load_stage(1, 1);

    for (int it = 0; it < NIT; ++it) {
        if (NSTAGE == 3) {
            if (it + 2 < NIT) { load_stage(it + 2, (it + 2) % 3); CP_WAIT(2); }
            else if (it + 1 < NIT) { CP_WAIT(1); }
            else { CP_WAIT(0); }
        } else {
            if (it + 1 < NIT) { load_stage(it + 1, (it + 1) & 1); CP_WAIT(1); }
            else { CP_WAIT(0); }
        }
        __syncthreads();

        uint32_t stg = sbase + (uint32_t)(it % NSTAGE) * STAGE;
        const uint32_t sA = stg;
        const uint32_t sBhi = stg + TILE_BYTES;
        const uint32_t sBlo = stg + 2 * TILE_BYTES;

        #pragma unroll
        for (int ks = 0; ks < 4; ks++) {
            uint32_t a[2][4];
            #pragma unroll
            for (int mt = 0; mt < 2; mt++) {
                uint32_t off = sw128((uint32_t)((rowA + mt * 16) * 128 + ks * 32 + kbA));
                ldmx4(a[mt][0], a[mt][1], a[mt][2], a[mt][3], sA + off);
            }
            uint32_t bh[8][2];
            #pragma unroll
            for (int p = 0; p < 4; p++) {
                uint32_t off = sw128((uint32_t)((rowB + p * 16) * 128 + ks * 32 + kbB));
                ldmx4(bh[2*p][0], bh[2*p][1], bh[2*p+1][0], bh[2*p+1][1], sBhi + off);
            }
            #pragma unroll
            for (int mt = 0; mt < 2; mt++)
                #pragma unroll
                for (int nt = 0; nt < 8; nt++)
                    mma_f16(d[mt][nt], a[mt], bh[nt]);
            if (NPROD == 2) {
                uint32_t bl[8][2];
                #pragma unroll
                for (int p = 0; p < 4; p++) {
                    uint32_t off = sw128((uint32_t)((rowB + p * 16) * 128 + ks * 32 + kbB));
                    ldmx4(bl[2*p][0], bl[2*p][1], bl[2*p+1][0], bl[2*p+1][1], sBlo + off);
                }
                #pragma unroll
                for (int mt = 0; mt < 2; mt++)
                    #pragma unroll
                    for (int nt = 0; nt < 8; nt++)
                        mma_f16(d[mt][nt], a[mt], bl[nt]);
            }
        }
        __syncthreads();
    }

    const int q = lane >> 2, c2 = (lane & 3) * 2;
    #pragma unroll
    for (int mt = 0; mt < 2; mt++) {
        int m0 = blockM + wm * 32 + mt * 16 + q;
        #pragma unroll
        for (int nt = 0; nt < 8; nt++) {
            int col = blockN + wn * 64 + nt * 8 + c2;
            *(float2*)&C[(size_t)m0 * NHIDD + col] = make_float2(d[mt][nt][0], d[mt][nt][1]);
            *(float2*)&C[(size_t)(m0 + 8) * NHIDD + col] = make_float2(d[mt][nt][2], d[mt][nt][3]);
        }
    }
}

// ---- layer-1 epilogue + Z = H@W2 fused (sums raw ACC partials, applies drow)
__global__ void epi2_kernel(const float* __restrict__ ACC0, const float* __restrict__ ACC1,
                            const float* __restrict__ X1,
                            const float* __restrict__ T1, const float* __restrict__ W2,
                            const float* __restrict__ drow, const float* __restrict__ dcol,
                            float2* __restrict__ Z, float2* __restrict__ Zc) {
    int warp = threadIdx.x >> 5, lane = threadIdx.x & 31;
    int row = blockIdx.x * 8 + warp;
    size_t base = (size_t)row * NHIDD;
    float dr = drow[row];
    float z0 = 0.f, z1 = 0.f;
    #pragma unroll
    for (int b = 0; b < 2; b++) {
        int n0 = lane * 8 + b * 4;
        float4 a0 = *(const float4*)&ACC0[base + n0];
        float4 a1 = *(const float4*)&ACC1[base + n0];
        float4 xv = *(const float4*)&X1[base + n0];
        float4 tv = *(const float4*)&T1[base + n0];
        float as[4] = {dr * (a0.x + a1.x), dr * (a0.y + a1.y),
                       dr * (a0.z + a1.z), dr * (a0.w + a1.w)};
        float xs[4] = {xv.x, xv.y, xv.z, xv.w};
        float ts[4] = {tv.x, tv.y, tv.z, tv.w};
        #pragma unroll
        for (int e = 0; e < 4; e++) {
            float h = 0.5f * xs[e] - 0.5f * ts[e] - as[e];
            h = h > 0.f ? h : 0.f;
            int n = n0 + e;
            z0 = fmaf(h, W2[2 * n], z0);
            z1 = fmaf(h, W2[2 * n + 1], z1);
        }
    }
    #pragma unroll
    for (int o = 16; o > 0; o >>= 1) {
        z0 += __shfl_xor_sync(0xffffffffu, z0, o);
        z1 += __shfl_xor_sync(0xffffffffu, z1, o);
    }
    if (lane == 0) {
        Z[row] = make_float2(z0, z1);
        float dc = dcol[row];
        Zc[row] = make_float2(dc * z0, dc * z1);
    }
}

// ---- U = drow ∘ (adj_h @ V), V [8192,2] already dcol-scaled -----------------
template<int FINAL>
__global__ void pv16(const __half* __restrict__ adjh, const float2* __restrict__ V,
                     const float2* __restrict__ Z, const float2* __restrict__ U1,
                     const float* __restrict__ b2,
                     const float* __restrict__ drow, const float* __restrict__ dcol,
                     float2* __restrict__ outU, float2* __restrict__ outUc,
                     float* __restrict__ out) {
    int warp = threadIdx.x >> 5, lane = threadIdx.x & 31;
    int row = blockIdx.x * 8 + warp;
    const uint4* ap = (const uint4*)(adjh + (size_t)row * NROWS);
    float ax = 0.f, ay = 0.f;
    #pragma unroll 1
    for (int ii = 0; ii < NROWS / 8; ii += 128) {
        uint4 q[4];
        #pragma unroll
        for (int j = 0; j < 4; j++)
            q[j] = __ldcs(&ap[ii + j * 32 + lane]);
        #pragma unroll
        for (int j = 0; j < 4; j++) {
            int k = (ii + j * 32 + lane) * 8;
            float2 f0 = __half22float2(*(__half2*)&q[j].x);
            float2 f1 = __half22float2(*(__half2*)&q[j].y);
            float2 f2 = __half22float2(*(__half2*)&q[j].z);
            float2 f3 = __half22float2(*(__half2*)&q[j].w);
            float2 v0 = V[k],     v1 = V[k + 1], v2 = V[k + 2], v3 = V[k + 3];
            float2 v4 = V[k + 4], v5 = V[k + 5], v6 = V[k + 6], v7 = V[k + 7];
            ax += f0.x * v0.x + f0.y * v1.x + f1.x * v2.x + f1.y * v3.x
                + f2.x * v4.x + f2.y * v5.x + f3.x * v6.x + f3.y * v7.x;
            ay += f0.x * v0.y + f0.y * v1.y + f1.x * v2.y + f1.y * v3.y
                + f2.x * v4.y + f2.y * v5.y + f3.x * v6.y + f3.y * v7.y;
        }
    }
    #pragma unroll
    for (int o = 16; o > 0; o >>= 1) {
        ax += __shfl_xor_sync(0xffffffffu, ax, o);
        ay += __shfl_xor_sync(0xffffffffu, ay, o);
    }
    if (lane == 0) {
        float dr = drow[row];
        float ux = dr * ax, uy = dr * ay;
        if (FINAL == 0) {
            outU[row] = make_float2(ux, uy);
            float dc = dcol[row];
            outUc[row] = make_float2(dc * ux, dc * uy);
        } else {
            float2 z = Z[row];
            float2 u1 = U1[row];
            float l0 = 0.5f * z.x - 0.5f * u1.x - ux + b2[0];
            float l1 = 0.5f * z.y - 0.5f * u1.y - uy + b2[1];
            float mx = fmaxf(l0, l1);
            float lse = mx + logf(expf(l0 - mx) + expf(l1 - mx));
            out[2 * row + 0] = l0 - lse;
            out[2 * row + 1] = l1 - lse;
        }
    }
}

// ---------------- launcher --------------------------------------------------
extern "C" void kernel_launch(void* const* d_in, const int* in_sizes, int n_in,
                              void* d_out, int out_size) {
    const float* x   = (const float*)d_in[0];
    const float* adj = (const float*)d_in[1];
    const float* W1  = (const float*)d_in[2];
    const float* W2  = (const float*)d_in[3];
    const float* b2  = (const float*)d_in[4];
    float* out = (float*)d_out;

    float *rowpart, *colpart, *drow, *dcol, *X1, *T1, *Part;
    __half *adjh, *xh, *W1Thi, *W1Tlo, *Bt1, *Bt2;
    float2 *Z, *Zc, *U1, *U1c;
    cudaGetSymbolAddress((void**)&rowpart, g_rowpart);
    cudaGetSymbolAddress((void**)&colpart, g_colpart);
    cudaGetSymbolAddress((void**)&drow,    g_drow);
    cudaGetSymbolAddress((void**)&dcol,    g_dcol);
    cudaGetSymbolAddress((void**)&X1,      g_X1);
    cudaGetSymbolAddress((void**)&T1,      g_T1);
    cudaGetSymbolAddress((void**)&Part,    g_Part);
    cudaGetSymbolAddress((void**)&adjh,    g_adjh);
    cudaGetSymbolAddress((void**)&xh,      g_xh);
    cudaGetSymbolAddress((void**)&W1Thi,   g_W1Thi);
    cudaGetSymbolAddress((void**)&W1Tlo,   g_W1Tlo);
    cudaGetSymbolAddress((void**)&Bt1,     g_Bt1);
    cudaGetSymbolAddress((void**)&Bt2,     g_Bt2);
    cudaGetSymbolAddress((void**)&Z,       g_Z);
    cudaGetSymbolAddress((void**)&Zc,      g_Zc);
    cudaGetSymbolAddress((void**)&U1,      g_U1);
    cudaGetSymbolAddress((void**)&U1c,     g_U1c);

    float* Part0 = Part;
    float* Part1 = Part + (size_t)NROWS * NHIDD;

    const int SM1 = 3 * TILE_BYTES * 2;   // gemmNP<1>: 98304
    const int SM2 = 2 * TILE_BYTES * 3;   // gemmNP<2>: 98304
    cudaFuncSetAttribute(gemmNP<1>, cudaFuncAttributeMaxDynamicSharedMemorySize, SM1);
    cudaFuncSetAttribute(gemmNP<2>, cudaFuncAttributeMaxDynamicSharedMemorySize, SM2);

    // Side stream + events for fork/join (host resources, created once).
    static cudaStream_t sB = nullptr;
    static cudaEvent_t eFork = nullptr, eX1 = nullptr;
    if (sB == nullptr) {
        cudaStreamCreateWithFlags(&sB, cudaStreamNonBlocking);
        cudaEventCreateWithFlags(&eFork, cudaEventDisableTiming);
        cudaEventCreateWithFlags(&eX1, cudaEventDisableTiming);
    }

    // ---- fork: x-chain on side stream (independent of adj) ----
    cudaEventRecord(eFork, 0);
    cudaStreamWaitEvent(sB, eFork, 0);
    convert_x<<<(NROWS * (NFEATD / 4)) / 256, 256, 0, sB>>>(x, xh);
    trans_split<true><<<dim3(NFEATD / 32, NHIDD / 32), dim3(32, 8), 0, sB>>>(
        W1, W1Thi, W1Tlo, nullptr, NHIDD);
    // X1 = x @ W1 (2-product, K=512)
    gemmNP<2><<<dim3(NROWS / 128, NHIDD / 128, 1), 256, SM2, sB>>>(
        xh, W1Thi, W1Tlo, X1, NFEATD);
    cudaEventRecord(eX1, sB);

    // ---- main stream: one adj pass => adj_h + sums; then dcol/drow ----
    fused_sum_convert<<<dim3(32, 64), 256>>>(adj, adjh, rowpart, colpart);
    dscale_kernel<<<NROWS / 256, 256>>>(rowpart, colpart, drow, dcol);

    // Bt1 = (dcol ∘ X1)^T fp16  (needs X1 + dcol)
    cudaStreamWaitEvent(0, eX1, 0);
    trans_split<false><<<dim3(NROWS / 32, NHIDD / 32), dim3(32, 8)>>>(
        X1, Bt1, nullptr, dcol, NHIDD);

    // raw T1 partials = adj_h @ Bt1^T (K-split=2)
    gemmNP<1><<<dim3(NROWS / 128, NHIDD / 128, 2), 256, SM1>>>(adjh, Bt1, nullptr, Part, NROWS);

    // T1 = drow∘(Part0+Part1); Bt2 = (dcol ∘ T1)^T fp16
    trans_combine<<<dim3(NROWS / 32, NHIDD / 32), dim3(32, 8)>>>(
        Part0, Part1, drow, dcol, T1, Bt2);

    // raw ACC partials = adj_h @ Bt2^T (K-split=2; consumed by epi2)
    gemmNP<1><<<dim3(NROWS / 128, NHIDD / 128, 2), 256, SM1>>>(adjh, Bt2, nullptr, Part, NROWS);

    // H = relu(0.5*X1 - 0.5*T1 - drow∘(ACC0+ACC1)); Z = H@W2; Zc = dcol∘Z
    epi2_kernel<<<NROWS / 8, 256>>>(Part0, Part1, X1, T1, W2, drow, dcol, Z, Zc);

    // U1 = drow ∘ (adj_h @ Zc); U1c = dcol∘U1
    pv16<0><<<NROWS / 8, 256>>>(adjh, Zc, nullptr, nullptr, nullptr, drow, dcol,
                                U1, U1c, nullptr);

    // out = log_softmax(0.5*Z - 0.5*U1 - drow∘(adj_h @ U1c) + b2)
    pv16<1><<<NROWS / 8, 256>>>(adjh, U1c, Z, U1, b2, drow, dcol,
                                nullptr, nullptr, out);
}

// round 16
// speedup vs baseline: 1.0739x; 1.0243x over previous
#include <cuda_runtime.h>
#include <cuda_fp16.h>
#include <math.h>
#include <stdint.h>

// MidGCN on GB300 (compute_103 PTX => mma.sync fp16 HMMA):
//   adj_f = 0.5*I - 0.5*P - P^2,  P = drow ∘ adj ∘ dcol
//   layer1: H = relu(0.5*X1 - 0.5*T1 - P@T1),  X1 = x@W1, T1 = P@X1
//   layer2: out = log_softmax(0.5*Z - 0.5*(P@Z) - P@(P@Z) + b2), Z = H@W2
// adj stored ONCE as unscaled fp16 (adj_h); drow/dcol folded into the skinny
// B operands and fp32 epilogues. fused_sum_convert is now SINGLE-PASS:
// row sums accumulated through smem during the convert loop (no re-read).
// Big GEMMs: single-product fp16 HMMA, BM=128 BN=128, K-SPLIT=2 (256 CTAs).

#define NROWS 8192
#define NHIDD 256
#define NFEATD 512

// ---------------- scratch (device globals) ----------------------------------
__device__ float g_rowpart[32 * NROWS];
__device__ float g_colpart[256 * NROWS];
__device__ float g_drow[NROWS];
__device__ float g_dcol[NROWS];
__device__ float g_X1[NROWS * NHIDD];
__device__ float g_T1[NROWS * NHIDD];
__device__ float g_Part[2 * NROWS * NHIDD];        // K-split partial outputs
__device__ __half g_adjh[(size_t)NROWS * NROWS];   // adj fp16 (unscaled)
__device__ __half g_xh[NROWS * NFEATD];            // x fp16
__device__ __half g_W1Thi[NHIDD * NFEATD];         // W1^T hi/lo
__device__ __half g_W1Tlo[NHIDD * NFEATD];
__device__ __half g_Bt1[NHIDD * NROWS];            // (dcol ∘ X1)^T fp16
__device__ __half g_Bt2[NHIDD * NROWS];            // (dcol ∘ T1)^T fp16
__device__ float2 g_Z  [NROWS];
__device__ float2 g_Zc [NROWS];
__device__ float2 g_U1 [NROWS];
__device__ float2 g_U1c[NROWS];

// ---------------- helpers ----------------------------------------------------
__device__ __forceinline__ uint32_t smem_u32(const void* p) {
    return (uint32_t)__cvta_generic_to_shared(p);
}
__device__ __forceinline__ void cp16(uint32_t s, const void* g) {
    asm volatile("cp.async.cg.shared.global [%0], [%1], 16;"
                 :: "r"(s), "l"(__cvta_generic_to_global(g)) : "memory");
}
#define CP_COMMIT() asm volatile("cp.async.commit_group;" ::: "memory")
#define CP_WAIT(n)  asm volatile("cp.async.wait_group %0;" :: "n"(n) : "memory")

__device__ __forceinline__ void ldmx4(uint32_t& r0, uint32_t& r1, uint32_t& r2, uint32_t& r3,
                                      uint32_t addr) {
    asm volatile("ldmatrix.sync.aligned.m8n8.x4.shared.b16 {%0,%1,%2,%3}, [%4];"
                 : "=r"(r0), "=r"(r1), "=r"(r2), "=r"(r3) : "r"(addr));
}
__device__ __forceinline__ void mma_f16(float* d, const uint32_t* a, const uint32_t* b) {
    asm volatile(
        "mma.sync.aligned.m16n8k16.row.col.f32.f16.f16.f32 "
        "{%0,%1,%2,%3}, {%4,%5,%6,%7}, {%8,%9}, {%0,%1,%2,%3};"
        : "+f"(d[0]), "+f"(d[1]), "+f"(d[2]), "+f"(d[3])
        : "r"(a[0]), "r"(a[1]), "r"(a[2]), "r"(a[3]), "r"(b[0]), "r"(b[1]));
}
__device__ __forceinline__ uint32_t sw128(uint32_t off) {
    return off ^ ((off >> 3) & 0x70);
}

// ---- fused SINGLE-PASS: adj -> adj_h (fp16) + row/col partial sums ----------
// Tile 128 rows x 256 cols per CTA (grid 32 x 64). Each thread: 32 rows of
// one float4 column-group. Row partials go through smem (racc), no re-read.
__global__ __launch_bounds__(256, 4)
void fused_sum_convert(const float* __restrict__ adj, __half* __restrict__ adjh,
                       float* __restrict__ rowpart, float* __restrict__ colpart) {
    __shared__ float racc[4][32][65];
    int cb = blockIdx.x;          // 0..31 (256-col stripe)
    int rb = blockIdx.y;          // 0..63 (128-row stripe)
    int sub = threadIdx.x >> 6;   // 0..3  (row subgroup)
    int cg  = threadIdx.x & 63;   // 0..63 (float4 col-group in stripe)
    int c4 = cb * 64 + cg;
    int r0 = rb * 128 + sub * 32;
    const float4* src = (const float4*)adj;
    uint2* dst = (uint2*)adjh;
    float4 cs = make_float4(0.f, 0.f, 0.f, 0.f);
    #pragma unroll 8
    for (int i = 0; i < 32; i++) {
        size_t idx = (size_t)(r0 + i) * (NROWS / 4) + c4;
        float4 v = __ldcs(&src[idx]);
        cs.x += v.x; cs.y += v.y; cs.z += v.z; cs.w += v.w;
        racc[sub][i][cg] = (v.x + v.y) + (v.z + v.w);
        __half2 h0 = __floats2half2_rn(v.x, v.y);
        __half2 h1 = __floats2half2_rn(v.z, v.w);
        uint2 o;
        o.x = *(uint32_t*)&h0;
        o.y = *(uint32_t*)&h1;
        __stcs(&dst[idx], o);
    }
    ((float4*)&colpart[(size_t)(rb * 4 + sub) * NROWS])[c4] = cs;
    __syncthreads();
    if (threadIdx.x < 128) {
        int s2 = threadIdx.x >> 5, rl = threadIdx.x & 31;
        float t = 0.f;
        #pragma unroll 16
        for (int g = 0; g < 64; g++) t += racc[s2][rl][g];
        rowpart[(size_t)cb * NROWS + rb * 128 + threadIdx.x] = t;
    }
}

// drow/dcol = sum^-0.5 (inf -> 0)
__global__ void dscale_kernel(const float* __restrict__ rowpart, const float* __restrict__ colpart,
                              float* __restrict__ drow, float* __restrict__ dcol) {
    int i = blockIdx.x * 256 + threadIdx.x;
    float rs = 0.f;
    #pragma unroll
    for (int p = 0; p < 32; p++) rs += rowpart[(size_t)p * NROWS + i];
    drow[i] = rs > 0.f ? rsqrtf(rs) : 0.f;
    float cs = 0.f;
    #pragma unroll 16
    for (int p = 0; p < 256; p++) cs += colpart[(size_t)p * NROWS + i];
    dcol[i] = cs > 0.f ? rsqrtf(cs) : 0.f;
}

// ---------------- x -> fp16 --------------------------------------------------
__global__ void convert_x(const float* __restrict__ x, __half* __restrict__ xh) {
    size_t i4 = (size_t)blockIdx.x * 256 + threadIdx.x;
    float4 v = ((const float4*)x)[i4];
    __half2 h0 = __floats2half2_rn(v.x, v.y);
    __half2 h1 = __floats2half2_rn(v.z, v.w);
    uint2 o;
    o.x = *(uint32_t*)&h0;
    o.y = *(uint32_t*)&h1;
    ((uint2*)xh)[i4] = o;
}

// ---- transpose + fp16 split; optional per-source-row scale (rowScale) -------
template<bool WRITE_LO>
__global__ void trans_split(const float* __restrict__ src,
                            __half* __restrict__ hi, __half* __restrict__ lo,
                            const float* __restrict__ rowScale, int srcN) {
    __shared__ float tile[32][33];
    int m0 = blockIdx.x * 32, n0 = blockIdx.y * 32;
    int dstStride = gridDim.x * 32;
    int tx = threadIdx.x, ty = threadIdx.y;   // 32 x 8
    #pragma unroll
    for (int j = 0; j < 4; j++)
        tile[ty + j * 8][tx] = src[(size_t)(m0 + ty + j * 8) * srcN + n0 + tx];
    __syncthreads();
    float rs = rowScale ? rowScale[m0 + tx] : 1.0f;
    #pragma unroll
    for (int j = 0; j < 4; j++) {
        int n = n0 + ty + j * 8;
        float v = tile[tx][ty + j * 8] * rs;
        __half h = __float2half_rn(v);
        size_t o = (size_t)n * dstStride + m0 + tx;
        hi[o] = h;
        if (WRITE_LO) lo[o] = __float2half_rn(v - __half2float(h));
    }
}

// ---- fused: T1 = drow∘(Part0+Part1); Bt2 = (dcol ∘ T1)^T fp16 ---------------
__global__ void trans_combine(const float* __restrict__ p0, const float* __restrict__ p1,
                              const float* __restrict__ drow, const float* __restrict__ dcol,
                              float* __restrict__ T1, __half* __restrict__ Bt) {
    __shared__ float tile[32][33];
    int m0 = blockIdx.x * 32, n0 = blockIdx.y * 32;
    int tx = threadIdx.x, ty = threadIdx.y;   // 32 x 8
    #pragma unroll
    for (int j = 0; j < 4; j++) {
        int m = m0 + ty + j * 8;
        size_t idx = (size_t)m * NHIDD + n0 + tx;
        float v = drow[m] * (p0[idx] + p1[idx]);
        tile[ty + j * 8][tx] = v;
        T1[idx] = v;
    }
    __syncthreads();
    float dc = dcol[m0 + tx];
    #pragma unroll
    for (int j = 0; j < 4; j++) {
        int n = n0 + ty + j * 8;
        float v = tile[tx][ty + j * 8] * dc;
        Bt[(size_t)n * NROWS + m0 + tx] = __float2half_rn(v);
    }
}

// ---------------- HMMA GEMM: C[128x128/CTA] = A_f16 @ (Bhi [+ Blo])^T -------
// BM=128, BN=128, BK=64, SW128 smem, 8 warps (4M x 2N), warp tile 32x64.
// NPROD=1: 3-stage pipeline; NPROD=2: 2-stage.
// blockIdx.z = K-split index (Ksub = K / gridDim.z), output slab per z.
#define GK 64
#define TILE_BYTES 16384                 // 128 rows * 128B

template<int NPROD>
__global__ __launch_bounds__(256, 2)
void gemmNP(const __half* __restrict__ A_g,
            const __half* __restrict__ Bhi_g, const __half* __restrict__ Blo_g,
            float* __restrict__ C_g, int K) {
    const int STAGE = TILE_BYTES * (1 + NPROD);
    const int NSTAGE = (NPROD == 1) ? 3 : 2;
    extern __shared__ __align__(1024) char smem[];
    const int tid = threadIdx.x, lane = tid & 31, wid = tid >> 5;
    const int wm = wid >> 1;          // 0..3
    const int wn = wid & 1;           // 0..1
    const int blockM = blockIdx.x * 128;
    const int blockN = blockIdx.y * 128;
    const int Ksub = K / gridDim.z;
    const int kBase = blockIdx.z * Ksub;
    float* C = C_g + (size_t)blockIdx.z * NROWS * NHIDD;
    const uint32_t sbase = smem_u32(smem);

    const __half* A   = A_g   + (size_t)blockM * K;
    const __half* Bhi = Bhi_g + (size_t)blockN * K;
    const __half* Blo = (NPROD == 2) ? Blo_g + (size_t)blockN * K : nullptr;

    float d[2][8][4];
    #pragma unroll
    for (int mt = 0; mt < 2; mt++)
        #pragma unroll
        for (int nt = 0; nt < 8; nt++)
            #pragma unroll
            for (int e = 0; e < 4; e++) d[mt][nt][e] = 0.f;

    auto load_stage = [&](int it, int buf) {
        uint32_t stg = sbase + (uint32_t)buf * STAGE;
        int k0 = kBase + it * GK;
        #pragma unroll
        for (int idx = tid; idx < 1024; idx += 256) {
            int row = idx >> 3, g = idx & 7;
            cp16(stg + sw128((uint32_t)(row * 128 + g * 16)),
                 A + (size_t)row * K + k0 + g * 8);
        }
        #pragma unroll
        for (int idx = tid; idx < 1024; idx += 256) {
            int row = idx >> 3, g = idx & 7;
            cp16(stg + TILE_BYTES + sw128((uint32_t)(row * 128 + g * 16)),
                 Bhi + (size_t)row * K + k0 + g * 8);
        }
        if (NPROD == 2) {
            #pragma unroll
            for (int idx = tid; idx < 1024; idx += 256) {
                int row = idx >> 3, g = idx & 7;
                cp16(stg + 2 * TILE_BYTES + sw128((uint32_t)(row * 128 + g * 16)),
                     Blo + (size_t)row * K + k0 + g * 8);
            }
        }
        CP_COMMIT();
    };

    const int rowA = wm * 32 + (lane & 15);
    const int kbA  = (lane >> 4) * 16;
    const int rowB = wn * 64 + (lane & 7) + ((lane >> 4) & 1) * 8;
    const int kbB  = ((lane >> 3) & 1) * 16;

    const int NIT = Ksub / GK;
    load_stage(0, 0);
    if (NSTAGE == 3) load_stage(1, 1);

    for (int it = 0; it < NIT; ++it) {
        if (NSTAGE == 3) {
            if (it + 2 < NIT) { load_stage(it + 2, (it + 2) % 3); CP_WAIT(2); }
            else if (it + 1 < NIT) { CP_WAIT(1); }
            else { CP_WAIT(0); }
        } else {
            if (it + 1 < NIT) { load_stage(it + 1, (it + 1) & 1); CP_WAIT(1); }
            else { CP_WAIT(0); }
        }
        __syncthreads();

        uint32_t stg = sbase + (uint32_t)(it % NSTAGE) * STAGE;
        const uint32_t sA = stg;
        const uint32_t sBhi = stg + TILE_BYTES;
        const uint32_t sBlo = stg + 2 * TILE_BYTES;

        #pragma unroll
        for (int ks = 0; ks < 4; ks++) {
            uint32_t a[2][4];
            #pragma unroll
            for (int mt = 0; mt < 2; mt++) {
                uint32_t off = sw128((uint32_t)((rowA + mt * 16) * 128 + ks * 32 + kbA));
                ldmx4(a[mt][0], a[mt][1], a[mt][2], a[mt][3], sA + off);
            }
            uint32_t bh[8][2];
            #pragma unroll
            for (int p = 0; p < 4; p++) {
                uint32_t off = sw128((uint32_t)((rowB + p * 16) * 128 + ks * 32 + kbB));
                ldmx4(bh[2*p][0], bh[2*p][1], bh[2*p+1][0], bh[2*p+1][1], sBhi + off);
            }
            #pragma unroll
            for (int mt = 0; mt < 2; mt++)
                #pragma unroll
                for (int nt = 0; nt < 8; nt++)
                    mma_f16(d[mt][nt], a[mt], bh[nt]);
            if (NPROD == 2) {
                uint32_t bl[8][2];
                #pragma unroll
                for (int p = 0; p < 4; p++) {
                    uint32_t off = sw128((uint32_t)((rowB + p * 16) * 128 + ks * 32 + kbB));
                    ldmx4(bl[2*p][0], bl[2*p][1], bl[2*p+1][0], bl[2*p+1][1], sBlo + off);
                }
                #pragma unroll
                for (int mt = 0; mt < 2; mt++)
                    #pragma unroll
                    for (int nt = 0; nt < 8; nt++)
                        mma_f16(d[mt][nt], a[mt], bl[nt]);
            }
        }
        __syncthreads();
    }

    const int q = lane >> 2, c2 = (lane & 3) * 2;
    #pragma unroll
    for (int mt = 0; mt < 2; mt++) {
        int m0 = blockM + wm * 32 + mt * 16 + q;
        #pragma unroll
        for (int nt = 0; nt < 8; nt++) {
            int col = blockN + wn * 64 + nt * 8 + c2;
            *(float2*)&C[(size_t)m0 * NHIDD + col] = make_float2(d[mt][nt][0], d[mt][nt][1]);
            *(float2*)&C[(size_t)(m0 + 8) * NHIDD + col] = make_float2(d[mt][nt][2], d[mt][nt][3]);
        }
    }
}

// ---- layer-1 epilogue + Z = H@W2 fused (sums raw ACC partials, applies drow)
__global__ void epi2_kernel(const float* __restrict__ ACC0, const float* __restrict__ ACC1,
                            const float* __restrict__ X1,
                            const float* __restrict__ T1, const float* __restrict__ W2,
                            const float* __restrict__ drow, const float* __restrict__ dcol,
                            float2* __restrict__ Z, float2* __restrict__ Zc) {
    int warp = threadIdx.x >> 5, lane = threadIdx.x & 31;
    int row = blockIdx.x * 8 + warp;
    size_t base = (size_t)row * NHIDD;
    float dr = drow[row];
    float z0 = 0.f, z1 = 0.f;
    #pragma unroll
    for (int b = 0; b < 2; b++) {
        int n0 = lane * 8 + b * 4;
        float4 a0 = *(const float4*)&ACC0[base + n0];
        float4 a1 = *(const float4*)&ACC1[base + n0];
        float4 xv = *(const float4*)&X1[base + n0];
        float4 tv = *(const float4*)&T1[base + n0];
        float as[4] = {dr * (a0.x + a1.x), dr * (a0.y + a1.y),
                       dr * (a0.z + a1.z), dr * (a0.w + a1.w)};
        float xs[4] = {xv.x, xv.y, xv.z, xv.w};
        float ts[4] = {tv.x, tv.y, tv.z, tv.w};
        #pragma unroll
        for (int e = 0; e < 4; e++) {
            float h = 0.5f * xs[e] - 0.5f * ts[e] - as[e];
            h = h > 0.f ? h : 0.f;
            int n = n0 + e;
            z0 = fmaf(h, W2[2 * n], z0);
            z1 = fmaf(h, W2[2 * n + 1], z1);
        }
    }
    #pragma unroll
    for (int o = 16; o > 0; o >>= 1) {
        z0 += __shfl_xor_sync(0xffffffffu, z0, o);
        z1 += __shfl_xor_sync(0xffffffffu, z1, o);
    }
    if (lane == 0) {
        Z[row] = make_float2(z0, z1);
        float dc = dcol[row];
        Zc[row] = make_float2(dc * z0, dc * z1);
    }
}

// ---- U = drow ∘ (adj_h @ V), V [8192,2] already dcol-scaled -----------------
template<int FINAL>
__global__ void pv16(const __half* __restrict__ adjh, const float2* __restrict__ V,
                     const float2* __restrict__ Z, const float2* __restrict__ U1,
                     const float* __restrict__ b2,
                     const float* __restrict__ drow, const float* __restrict__ dcol,
                     float2* __restrict__ outU, float2* __restrict__ outUc,
                     float* __restrict__ out) {
    int warp = threadIdx.x >> 5, lane = threadIdx.x & 31;
    int row = blockIdx.x * 8 + warp;
    const uint4* ap = (const uint4*)(adjh + (size_t)row * NROWS);
    float ax = 0.f, ay = 0.f;
    #pragma unroll 1
    for (int ii = 0; ii < NROWS / 8; ii += 128) {
        uint4 q[4];
        #pragma unroll
        for (int j = 0; j < 4; j++)
            q[j] = __ldcs(&ap[ii + j * 32 + lane]);
        #pragma unroll
        for (int j = 0; j < 4; j++) {
            int k = (ii + j * 32 + lane) * 8;
            float2 f0 = __half22float2(*(__half2*)&q[j].x);
            float2 f1 = __half22float2(*(__half2*)&q[j].y);
            float2 f2 = __half22float2(*(__half2*)&q[j].z);
            float2 f3 = __half22float2(*(__half2*)&q[j].w);
            float2 v0 = V[k],     v1 = V[k + 1], v2 = V[k + 2], v3 = V[k + 3];
            float2 v4 = V[k + 4], v5 = V[k + 5], v6 = V[k + 6], v7 = V[k + 7];
            ax += f0.x * v0.x + f0.y * v1.x + f1.x * v2.x + f1.y * v3.x
                + f2.x * v4.x + f2.y * v5.x + f3.x * v6.x + f3.y * v7.x;
            ay += f0.x * v0.y + f0.y * v1.y + f1.x * v2.y + f1.y * v3.y
                + f2.x * v4.y + f2.y * v5.y + f3.x * v6.y + f3.y * v7.y;
        }
    }
    #pragma unroll
    for (int o = 16; o > 0; o >>= 1) {
        ax += __shfl_xor_sync(0xffffffffu, ax, o);
        ay += __shfl_xor_sync(0xffffffffu, ay, o);
    }
    if (lane == 0) {
        float dr = drow[row];
        float ux = dr * ax, uy = dr * ay;
        if (FINAL == 0) {
            outU[row] = make_float2(ux, uy);
            float dc = dcol[row];
            outUc[row] = make_float2(dc * ux, dc * uy);
        } else {
            float2 z = Z[row];
            float2 u1 = U1[row];
            float l0 = 0.5f * z.x - 0.5f * u1.x - ux + b2[0];
            float l1 = 0.5f * z.y - 0.5f * u1.y - uy + b2[1];
            float mx = fmaxf(l0, l1);
            float lse = mx + logf(expf(l0 - mx) + expf(l1 - mx));
            out[2 * row + 0] = l0 - lse;
            out[2 * row + 1] = l1 - lse;
        }
    }
}

// ---------------- launcher --------------------------------------------------
extern "C" void kernel_launch(void* const* d_in, const int* in_sizes, int n_in,
                              void* d_out, int out_size) {
    const float* x   = (const float*)d_in[0];
    const float* adj = (const float*)d_in[1];
    const float* W1  = (const float*)d_in[2];
    const float* W2  = (const float*)d_in[3];
    const float* b2  = (const float*)d_in[4];
    float* out = (float*)d_out;

    float *rowpart, *colpart, *drow, *dcol, *X1, *T1, *Part;
    __half *adjh, *xh, *W1Thi, *W1Tlo, *Bt1, *Bt2;
    float2 *Z, *Zc, *U1, *U1c;
    cudaGetSymbolAddress((void**)&rowpart, g_rowpart);
    cudaGetSymbolAddress((void**)&colpart, g_colpart);
    cudaGetSymbolAddress((void**)&drow,    g_drow);
    cudaGetSymbolAddress((void**)&dcol,    g_dcol);
    cudaGetSymbolAddress((void**)&X1,      g_X1);
    cudaGetSymbolAddress((void**)&T1,      g_T1);
    cudaGetSymbolAddress((void**)&Part,    g_Part);
    cudaGetSymbolAddress((void**)&adjh,    g_adjh);
    cudaGetSymbolAddress((void**)&xh,      g_xh);
    cudaGetSymbolAddress((void**)&W1Thi,   g_W1Thi);
    cudaGetSymbolAddress((void**)&W1Tlo,   g_W1Tlo);
    cudaGetSymbolAddress((void**)&Bt1,     g_Bt1);
    cudaGetSymbolAddress((void**)&Bt2,     g_Bt2);
    cudaGetSymbolAddress((void**)&Z,       g_Z);
    cudaGetSymbolAddress((void**)&Zc,      g_Zc);
    cudaGetSymbolAddress((void**)&U1,      g_U1);
    cudaGetSymbolAddress((void**)&U1c,     g_U1c);

    float* Part0 = Part;
    float* Part1 = Part + (size_t)NROWS * NHIDD;

    const int SM1 = 3 * TILE_BYTES * 2;   // gemmNP<1>: 98304
    const int SM2 = 2 * TILE_BYTES * 3;   // gemmNP<2>: 98304
    cudaFuncSetAttribute(gemmNP<1>, cudaFuncAttributeMaxDynamicSharedMemorySize, SM1);
    cudaFuncSetAttribute(gemmNP<2>, cudaFuncAttributeMaxDynamicSharedMemorySize, SM2);

    // Side stream + events for fork/join (host resources, created once).
    static cudaStream_t sB = nullptr;
    static cudaEvent_t eFork = nullptr, eX1 = nullptr;
    if (sB == nullptr) {
        cudaStreamCreateWithFlags(&sB, cudaStreamNonBlocking);
        cudaEventCreateWithFlags(&eFork, cudaEventDisableTiming);
        cudaEventCreateWithFlags(&eX1, cudaEventDisableTiming);
    }

    // ---- fork: x-chain on side stream (independent of adj) ----
    cudaEventRecord(eFork, 0);
    cudaStreamWaitEvent(sB, eFork, 0);
    convert_x<<<(NROWS * (NFEATD / 4)) / 256, 256, 0, sB>>>(x, xh);
    trans_split<true><<<dim3(NFEATD / 32, NHIDD / 32), dim3(32, 8), 0, sB>>>(
        W1, W1Thi, W1Tlo, nullptr, NHIDD);
    // X1 = x @ W1 (2-product, K=512)
    gemmNP<2><<<dim3(NROWS / 128, NHIDD / 128, 1), 256, SM2, sB>>>(
        xh, W1Thi, W1Tlo, X1, NFEATD);
    cudaEventRecord(eX1, sB);

    // ---- main stream: one adj pass => adj_h + sums; then dcol/drow ----
    fused_sum_convert<<<dim3(32, 64), 256>>>(adj, adjh, rowpart, colpart);
    dscale_kernel<<<NROWS / 256, 256>>>(rowpart, colpart, drow, dcol);

    // Bt1 = (dcol ∘ X1)^T fp16  (needs X1 + dcol)
    cudaStreamWaitEvent(0, eX1, 0);
    trans_split<false><<<dim3(NROWS / 32, NHIDD / 32), dim3(32, 8)>>>(
        X1, Bt1, nullptr, dcol, NHIDD);

    // raw T1 partials = adj_h @ Bt1^T (K-split=2)
    gemmNP<1><<<dim3(NROWS / 128, NHIDD / 128, 2), 256, SM1>>>(adjh, Bt1, nullptr, Part, NROWS);

    // T1 = drow∘(Part0+Part1); Bt2 = (dcol ∘ T1)^T fp16
    trans_combine<<<dim3(NROWS / 32, NHIDD / 32), dim3(32, 8)>>>(
        Part0, Part1, drow, dcol, T1, Bt2);

    // raw ACC partials = adj_h @ Bt2^T (K-split=2; consumed by epi2)
    gemmNP<1><<<dim3(NROWS / 128, NHIDD / 128, 2), 256, SM1>>>(adjh, Bt2, nullptr, Part, NROWS);

    // H = relu(0.5*X1 - 0.5*T1 - drow∘(ACC0+ACC1)); Z = H@W2; Zc = dcol∘Z
    epi2_kernel<<<NROWS / 8, 256>>>(Part0, Part1, X1, T1, W2, drow, dcol, Z, Zc);

    // U1 = drow ∘ (adj_h @ Zc); U1c = dcol∘U1
    pv16<0><<<NROWS / 8, 256>>>(adjh, Zc, nullptr, nullptr, nullptr, drow, dcol,
                                U1, U1c, nullptr);

    // out = log_softmax(0.5*Z - 0.5*U1 - drow∘(adj_h @ U1c) + b2)
    pv16<1><<<NROWS / 8, 256>>>(adjh, U1c, Z, U1, b2, drow, dcol,
                                nullptr, nullptr, out);
}